// round 13
// baseline (speedup 1.0000x reference)
#include <cuda_runtime.h>
#include <cuda.h>
#include <cuda_fp16.h>
#include <cstdint>

// ---------------- problem dims ----------------
static constexpr int BB   = 8192;
static constexpr int DD   = 1024;
static constexpr int HDIM = 1024;
static constexpr int KK   = 2048;   // 2*D  (x|h)
static constexpr int NN   = 4096;   // 4*H  (gate-interleaved: col = 4*h + gate)

// ---------------- GEMM tiling ----------------
static constexpr int BM = 128;
static constexpr int BN = 128;
static constexpr int BK = 64;                 // fp16 per K chunk = 128B row
static constexpr int K_ITERS = KK / BK;       // 32
static constexpr int STAGES  = 3;

static constexpr int A_STG = BM * 128;        // 16 KB
static constexpr int B_STG = BN * 128;        // 16 KB
static constexpr int STGB  = A_STG + B_STG;   // 32 KB
static constexpr int OFF_MBAR = STAGES * STGB;            // 98304
static constexpr int SMEM_DYN = OFF_MBAR + 64 + 1024;

// epilogue staging (float indices into smem, reusing stage buffers)
static constexpr int EPI_STRIDE = 36;                     // padded row stride (floats)
static constexpr int HSF  = 0;                            // h tile 128x32
static constexpr int CSF  = 128 * EPI_STRIDE;             // c tile
static constexpr int C1F  = 2 * 128 * EPI_STRIDE;         // c1 tile

// ---------------- scratch (static device arrays; no allocation) ----------------
__device__ __align__(1024) __half g_A[(size_t)BB * KK];   // 32 MB
__device__ __align__(1024) __half g_W[(size_t)NN * KK];   // 16 MB
__device__ float g_bias[NN];

// ---------------- PTX helpers ----------------
__device__ __forceinline__ uint32_t s2u(const void* p) {
    uint32_t a;
    asm("{ .reg .u64 t; cvta.to.shared.u64 t, %1; cvt.u32.u64 %0, t; }" : "=r"(a) : "l"(p));
    return a;
}
__device__ __forceinline__ void mbar_init(uint32_t a, uint32_t cnt) {
    asm volatile("mbarrier.init.shared.b64 [%0], %1;" :: "r"(a), "r"(cnt) : "memory");
}
__device__ __forceinline__ void mbar_expect_tx(uint32_t a, uint32_t bytes) {
    asm volatile("mbarrier.arrive.expect_tx.shared.b64 _, [%0], %1;" :: "r"(a), "r"(bytes) : "memory");
}
__device__ __forceinline__ void mbar_arrive(uint32_t a) {
    asm volatile("mbarrier.arrive.shared.b64 _, [%0];" :: "r"(a) : "memory");
}
__device__ __forceinline__ void mbar_wait(uint32_t a, uint32_t parity) {
    asm volatile(
        "{\n\t.reg .pred P;\n\t"
        "WL%=:\n\t"
        "mbarrier.try_wait.parity.acquire.cta.shared::cta.b64 P, [%0], %1, 0x989680;\n\t"
        "@P bra WD%=;\n\t"
        "bra WL%=;\n\t"
        "WD%=:\n\t}"
        :: "r"(a), "r"(parity) : "memory");
}
__device__ __forceinline__ void tma_2d(uint32_t dst, const CUtensorMap* map,
                                       int cx, int cy, uint32_t mbar) {
    asm volatile(
        "cp.async.bulk.tensor.2d.shared::cta.global.tile.mbarrier::complete_tx::bytes "
        "[%0], [%1, {%2, %3}], [%4];"
        :: "r"(dst), "l"(map), "r"(cx), "r"(cy), "r"(mbar) : "memory");
}
__device__ __forceinline__ void ldsm4(uint32_t (&r)[4], uint32_t a) {
    asm volatile("ldmatrix.sync.aligned.m8n8.x4.shared.b16 {%0,%1,%2,%3}, [%4];"
        : "=r"(r[0]), "=r"(r[1]), "=r"(r[2]), "=r"(r[3]) : "r"(a));
}
__device__ __forceinline__ void mma16816(float (&d)[4], const uint32_t (&a)[4],
                                         uint32_t b0, uint32_t b1) {
    asm volatile(
        "mma.sync.aligned.m16n8k16.row.col.f32.f16.f16.f32 "
        "{%0,%1,%2,%3}, {%4,%5,%6,%7}, {%8,%9}, {%0,%1,%2,%3};"
        : "+f"(d[0]), "+f"(d[1]), "+f"(d[2]), "+f"(d[3])
        : "r"(a[0]), "r"(a[1]), "r"(a[2]), "r"(a[3]), "r"(b0), "r"(b1));
}
__device__ __forceinline__ float4 ldcs4(const float* p) {
    float4 v;
    asm volatile("ld.global.cs.v4.f32 {%0,%1,%2,%3}, [%4];"
        : "=f"(v.x), "=f"(v.y), "=f"(v.z), "=f"(v.w) : "l"(p));
    return v;
}
__device__ __forceinline__ float sigf(float x) {
    return __fdividef(1.0f, 1.0f + __expf(-x));
}
__device__ __forceinline__ float tanh_acc(float x) {
    return __fmaf_rn(2.0f, sigf(2.0f * x), -1.0f);
}
__device__ __forceinline__ uint32_t packh2(float a, float b) {
    __half2 v = __floats2half2_rn(a, b);
    return *reinterpret_cast<uint32_t*>(&v);
}

// ---------------- merged prep kernel (2x 4xfloat4 per thread, MLP=8, .cs loads) ----------------
static constexpr int PREP_A_BLOCKS = BB * (KK / 32) / 256;   // 2048
static constexpr int PREP_W_BLOCKS = NN * (KK / 32) / 256;   // 1024

__device__ __forceinline__ void prep_seg16(const float* __restrict__ src,
                                           __half* __restrict__ dst) {
    float4 v0 = ldcs4(src);
    float4 v1 = ldcs4(src + 4);
    float4 v2 = ldcs4(src + 8);
    float4 v3 = ldcs4(src + 12);
    uint4 o0, o1;
    o0.x = packh2(v0.x, v0.y);
    o0.y = packh2(v0.z, v0.w);
    o0.z = packh2(v1.x, v1.y);
    o0.w = packh2(v1.z, v1.w);
    o1.x = packh2(v2.x, v2.y);
    o1.y = packh2(v2.z, v2.w);
    o1.z = packh2(v3.x, v3.y);
    o1.w = packh2(v3.z, v3.w);
    *reinterpret_cast<uint4*>(dst)     = o0;
    *reinterpret_cast<uint4*>(dst + 8) = o1;
}

__global__ void __launch_bounds__(256)
prep_all_kernel(const float* __restrict__ x, const float* __restrict__ h,
                const float* __restrict__ Wx, const float* __restrict__ bx,
                const float* __restrict__ Wh, const float* __restrict__ bh) {
    const int blk = blockIdx.x;
    if (blk < PREP_A_BLOCKS) {
        int gid = blk * 256 + threadIdx.x;        // over BB * (KK/32)
        int row = gid >> 6;                       // 64 segments of 32 per row
        int seg = gid & 63;
        int d0  = seg << 5;                       // 32 floats per thread
        // halves of KK: [0,1024) from x, [1024,2048) from h — d0 spans 32, never crosses
        const float* s = (d0 < DD) ? (x + (size_t)row * DD + d0)
                                   : (h + (size_t)row * DD + (d0 - DD));
        __half* dst = g_A + (size_t)row * KK + d0;
        prep_seg16(s, dst);
        prep_seg16(s + 16, dst + 16);
    } else {
        int gid = (blk - PREP_A_BLOCKS) * 256 + threadIdx.x;   // over NN * (KK/32)
        int row = gid >> 6;
        int seg = gid & 63;
        int d0  = seg << 5;
        int gate = row & 3;
        int hh   = row >> 2;
        int old  = (gate << 10) + hh;             // gate*1024 + h
        const float* s = (d0 < DD) ? (Wx + (size_t)old * DD + d0)
                                   : (Wh + (size_t)old * DD + (d0 - DD));
        __half* dst = g_W + (size_t)row * KK + d0;
        prep_seg16(s, dst);
        prep_seg16(s + 16, dst + 16);
        if (seg == 0) g_bias[row] = bx[old] + bh[old];
    }
}

// ---------------- fused GEMM + LSTM gate kernel ----------------
// Converged mainloop (R12) + register-prefetched epilogue with .cs c1 loads.
__global__ void __launch_bounds__(256, 2)
lstm_gemm_kernel(const __grid_constant__ CUtensorMap mapA,
                 const __grid_constant__ CUtensorMap mapB,
                 const float* __restrict__ c1_g,
                 float* __restrict__ h_out,
                 float* __restrict__ c_out) {
    extern __shared__ char smem_raw[];
    uint32_t s0   = s2u(smem_raw);
    uint32_t pad  = (1024u - (s0 & 1023u)) & 1023u;
    uint32_t sbase = s0 + pad;
    float* fbase = reinterpret_cast<float*>(smem_raw + pad);

    const int tid  = threadIdx.x;
    const int wid  = tid >> 5;
    const int lane = tid & 31;
    const int wm   = wid >> 1;            // 0..3 (m)
    const int wn   = wid & 1;             // 0..1 (n)
    const int m_base = blockIdx.y * BM;
    const int n_base = blockIdx.x * BN;
    const int h_base = blockIdx.x * (BN / 4);   // 32 h per tile

    const uint32_t FULL  = sbase + OFF_MBAR;          // full[s] : +8s
    const uint32_t EMPTY = sbase + OFF_MBAR + 8 * STAGES;

    if (tid == 0) {
        for (int s = 0; s < STAGES; s++) {
            mbar_init(FULL + 8 * s, 1);
            mbar_init(EMPTY + 8 * s, 8);   // one arrive per warp
        }
        asm volatile("fence.proxy.async.shared::cta;" ::: "memory");
    }
    __syncthreads();

    // prologue: fill stages 0,1
    if (tid == 0) {
        #pragma unroll
        for (int s = 0; s < STAGES - 1; s++) {
            mbar_expect_tx(FULL + 8 * s, (uint32_t)STGB);
            uint32_t dA = sbase + s * STGB;
            tma_2d(dA,         &mapA, s * BK, m_base, FULL + 8 * s);
            tma_2d(dA + A_STG, &mapB, s * BK, n_base, FULL + 8 * s);
        }
    }

    float acc[2][8][4];
    #pragma unroll
    for (int i = 0; i < 2; i++)
        #pragma unroll
        for (int j = 0; j < 8; j++)
            #pragma unroll
            for (int e = 0; e < 4; e++) acc[i][j][e] = 0.0f;

    const int lrow = lane & 15;     // ldmatrix row within 16
    const int lch  = lane >> 4;     // ldmatrix k half
    const int raA0 = wm * 32 + lrow;
    const int raA1 = raA0 + 16;
    const int rb0  = wn * 64 + lrow;

    // loop-invariant swizzled fragment offsets (stage-relative)
    const uint32_t offA0 = (uint32_t)(raA0 * 128) + (uint32_t)((lch ^ (raA0 & 7)) << 4);
    const uint32_t offA1 = (uint32_t)(raA1 * 128) + (uint32_t)((lch ^ (raA1 & 7)) << 4);
    uint32_t offB[4];
    #pragma unroll
    for (int nf2 = 0; nf2 < 4; nf2++) {
        int rb = rb0 + nf2 * 16;
        offB[nf2] = (uint32_t)A_STG + (uint32_t)(rb * 128)
                  + (uint32_t)((lch ^ (rb & 7)) << 4);
    }

    // fragment double buffers
    uint32_t a0b[2][4], a1b[2][4], bfb[2][4][4];

    int b = 0, phase = 0;   // consumer stage index / parity (incremental)

    for (int kb = 0; kb < K_ITERS; kb++) {
        // producer for stage kb+2 — rotating warp, BEFORE consuming FULL[b]
        if (wid == (kb & 7) && lane == 0) {
            int nf = kb + STAGES - 1;
            if (nf < K_ITERS) {
                int b2 = b + STAGES - 1;
                if (b2 >= STAGES) b2 -= STAGES;
                if (nf >= STAGES) {
                    mbar_wait(EMPTY + 8 * b2, ((nf - STAGES) / 3) & 1);
                }
                mbar_expect_tx(FULL + 8 * b2, (uint32_t)STGB);
                uint32_t dA = sbase + b2 * STGB;
                tma_2d(dA,         &mapA, nf * BK, m_base, FULL + 8 * b2);
                tma_2d(dA + A_STG, &mapB, nf * BK, n_base, FULL + 8 * b2);
            }
        }

        mbar_wait(FULL + 8 * b, phase);

        const uint32_t sA  = sbase + b * STGB;
        const uint32_t bA0 = sA + offA0;
        const uint32_t bA1 = sA + offA1;
        uint32_t bB[4];
        #pragma unroll
        for (int nf2 = 0; nf2 < 4; nf2++) bB[nf2] = sA + offB[nf2];

        // preload ks=0 fragments into buffer 0
        ldsm4(a0b[0], bA0);
        ldsm4(a1b[0], bA1);
        #pragma unroll
        for (int nf2 = 0; nf2 < 4; nf2++) ldsm4(bfb[0][nf2], bB[nf2]);

        #pragma unroll
        for (int ks = 0; ks < 4; ks++) {
            const int cur = ks & 1;
            if (ks < 3) {
                const uint32_t x5 = (uint32_t)((ks + 1) << 5);   // swizzle XOR step
                ldsm4(a0b[cur ^ 1], bA0 ^ x5);
                ldsm4(a1b[cur ^ 1], bA1 ^ x5);
                #pragma unroll
                for (int nf2 = 0; nf2 < 4; nf2++)
                    ldsm4(bfb[cur ^ 1][nf2], bB[nf2] ^ x5);
            }
            #pragma unroll
            for (int nf = 0; nf < 4; nf++) {
                mma16816(acc[0][2 * nf],     a0b[cur], bfb[cur][nf][0], bfb[cur][nf][2]);
                mma16816(acc[0][2 * nf + 1], a0b[cur], bfb[cur][nf][1], bfb[cur][nf][3]);
                mma16816(acc[1][2 * nf],     a1b[cur], bfb[cur][nf][0], bfb[cur][nf][2]);
                mma16816(acc[1][2 * nf + 1], a1b[cur], bfb[cur][nf][1], bfb[cur][nf][3]);
            }
        }
        if (lane == 0) mbar_arrive(EMPTY + 8 * b);

        if (++b == STAGES) { b = 0; phase ^= 1; }
    }

    // -------- epilogue (register-prefetched) --------
    const int t    = lane & 3;           // quad col pair: local cols 2t, 2t+1
    const int rowg = lane >> 2;
    const bool evenT = (t & 1) == 0;     // holds (gi, gf); odd holds (go, gc)

    // 1) prefetch c1 tile rows (coalesced, streaming) + per-thread bias into
    //    registers BEFORE the barrier — latency overlaps the straggler wait.
    float4 c1r[4];
    #pragma unroll
    for (int i = 0; i < 4; i++) {
        int idx = tid + i * 256;                 // 1024 = 128*8 float4 slots
        int row = idx >> 3;
        int q   = idx & 7;
        c1r[i] = ldcs4(c1_g + (size_t)(m_base + row) * HDIM + h_base + q * 4);
    }
    float2 biasr[8];
    #pragma unroll
    for (int nj = 0; nj < 8; nj++) {
        biasr[nj] = *reinterpret_cast<const float2*>(
            g_bias + n_base + wn * 64 + nj * 8 + 2 * t);
    }

    __syncthreads();   // mainloop done -> stage buffers reusable

    // 2) spill prefetched c1 to smem (shared-layout exchange)
    #pragma unroll
    for (int i = 0; i < 4; i++) {
        int idx = tid + i * 256;
        int row = idx >> 3;
        int q   = idx & 7;
        *reinterpret_cast<float4*>(fbase + C1F + row * EPI_STRIDE + q * 4) = c1r[i];
    }
    __syncthreads();

    #pragma unroll
    for (int mf = 0; mf < 2; mf++) {
        const int rl0 = wm * 32 + mf * 16 + rowg;   // local row
        const int rl1 = rl0 + 8;
        #pragma unroll
        for (int nj = 0; nj < 8; nj++) {
            const float2 bias = biasr[nj];
            float g0a = acc[mf][nj][0] + bias.x;
            float g1a = acc[mf][nj][1] + bias.y;
            float g0b = acc[mf][nj][2] + bias.x;
            float g1b = acc[mf][nj][3] + bias.y;

            float pa = sigf(g0a);
            float qa = evenT ? sigf(g1a) : tanh_acc(g1a);
            float pb = sigf(g0b);
            float qb = evenT ? sigf(g1b) : tanh_acc(g1b);

            float ov_a = __shfl_xor_sync(0xFFFFFFFFu, pa, 1);
            float ct_a = __shfl_xor_sync(0xFFFFFFFFu, qa, 1);
            float ov_b = __shfl_xor_sync(0xFFFFFFFFu, pb, 1);
            float ct_b = __shfl_xor_sync(0xFFFFFFFFu, qb, 1);

            const int hl = wn * 16 + nj * 2 + (t >> 1);
            float cna = 0.f, cnb = 0.f, hna = 0.f, hnb = 0.f;
            if (evenT) {
                float c1a = fbase[C1F + rl0 * EPI_STRIDE + hl];
                float c1b = fbase[C1F + rl1 * EPI_STRIDE + hl];
                cna = sigf(qa * c1a + pa * ct_a);
                cnb = sigf(qb * c1b + pb * ct_b);
                hna = tanh_acc(cna) * ov_a;
                hnb = tanh_acc(cnb) * ov_b;
            }
            float cna2 = __shfl_xor_sync(0xFFFFFFFFu, cna, 2);
            float cnb2 = __shfl_xor_sync(0xFFFFFFFFu, cnb, 2);
            float hna2 = __shfl_xor_sync(0xFFFFFFFFu, hna, 2);
            float hnb2 = __shfl_xor_sync(0xFFFFFFFFu, hnb, 2);
            if (t == 0) {
                const int c2 = wn * 16 + nj * 2;
                *reinterpret_cast<float2*>(fbase + HSF + rl0 * EPI_STRIDE + c2) =
                    make_float2(hna, hna2);
                *reinterpret_cast<float2*>(fbase + HSF + rl1 * EPI_STRIDE + c2) =
                    make_float2(hnb, hnb2);
                *reinterpret_cast<float2*>(fbase + CSF + rl0 * EPI_STRIDE + c2) =
                    make_float2(cna, cna2);
                *reinterpret_cast<float2*>(fbase + CSF + rl1 * EPI_STRIDE + c2) =
                    make_float2(cnb, cnb2);
            }
        }
    }
    __syncthreads();

    // coalesced global stores
    for (int idx = tid; idx < 128 * 8; idx += 256) {
        int row = idx >> 3;
        int q   = idx & 7;
        float4 hv = *reinterpret_cast<const float4*>(fbase + HSF + row * EPI_STRIDE + q * 4);
        float4 cv = *reinterpret_cast<const float4*>(fbase + CSF + row * EPI_STRIDE + q * 4);
        size_t off = (size_t)(m_base + row) * HDIM + h_base + q * 4;
        *reinterpret_cast<float4*>(h_out + off) = hv;
        *reinterpret_cast<float4*>(c_out + off) = cv;
    }
}

// ---------------- host launcher ----------------
typedef CUresult (*tme_fn_t)(CUtensorMap*, CUtensorMapDataType, cuuint32_t, void*,
                             const cuuint64_t*, const cuuint64_t*, const cuuint32_t*,
                             const cuuint32_t*, CUtensorMapInterleave, CUtensorMapSwizzle,
                             CUtensorMapL2promotion, CUtensorMapFloatOOBfill);

static tme_fn_t get_encoder() {
    void* fn = nullptr;
    cudaDriverEntryPointQueryResult qr;
#if CUDART_VERSION >= 12050
    cudaGetDriverEntryPointByVersion("cuTensorMapEncodeTiled", &fn, 12000,
                                     cudaEnableDefault, &qr);
#else
    cudaGetDriverEntryPoint("cuTensorMapEncodeTiled", &fn, cudaEnableDefault, &qr);
#endif
    return (tme_fn_t)fn;
}

extern "C" void kernel_launch(void* const* d_in, const int* in_sizes, int n_in,
                              void* d_out, int out_size) {
    const float* x  = (const float*)d_in[0];
    const float* h  = (const float*)d_in[1];
    const float* c1 = (const float*)d_in[2];
    const float* Wx = (const float*)d_in[3];
    const float* bx = (const float*)d_in[4];
    const float* Wh = (const float*)d_in[5];
    const float* bh = (const float*)d_in[6];
    float* h_out = (float*)d_out;
    float* c_out = h_out + (size_t)BB * HDIM;

    prep_all_kernel<<<PREP_A_BLOCKS + PREP_W_BLOCKS, 256>>>(x, h, Wx, bx, Wh, bh);

    void* aptr = nullptr; void* wptr = nullptr;
    cudaGetSymbolAddress(&aptr, g_A);
    cudaGetSymbolAddress(&wptr, g_W);
    tme_fn_t enc = get_encoder();
    if (!enc) return;

    CUtensorMap mapA, mapB;
    cuuint64_t dimsA[2] = {(cuuint64_t)KK, (cuuint64_t)BB};
    cuuint64_t strA[1]  = {(cuuint64_t)KK * 2};
    cuuint32_t boxA[2]  = {BK, BM};
    cuuint32_t es[2]    = {1, 1};
    enc(&mapA, CU_TENSOR_MAP_DATA_TYPE_FLOAT16, 2, aptr, dimsA, strA, boxA, es,
        CU_TENSOR_MAP_INTERLEAVE_NONE, CU_TENSOR_MAP_SWIZZLE_128B,
        CU_TENSOR_MAP_L2_PROMOTION_L2_128B, CU_TENSOR_MAP_FLOAT_OOB_FILL_NONE);

    cuuint64_t dimsB[2] = {(cuuint64_t)KK, (cuuint64_t)NN};
    cuuint32_t boxB[2]  = {BK, BN};
    enc(&mapB, CU_TENSOR_MAP_DATA_TYPE_FLOAT16, 2, wptr, dimsB, strA, boxB, es,
        CU_TENSOR_MAP_INTERLEAVE_NONE, CU_TENSOR_MAP_SWIZZLE_128B,
        CU_TENSOR_MAP_L2_PROMOTION_L2_128B, CU_TENSOR_MAP_FLOAT_OOB_FILL_NONE);

    cudaFuncSetAttribute(lstm_gemm_kernel,
                         cudaFuncAttributeMaxDynamicSharedMemorySize, SMEM_DYN);
    dim3 grid(NN / BN, BB / BM);   // (32, 64)
    lstm_gemm_kernel<<<grid, 256, SMEM_DYN>>>(mapA, mapB, c1, h_out, c_out);
}

// round 14
// speedup vs baseline: 1.0347x; 1.0347x over previous
#include <cuda_runtime.h>
#include <cuda.h>
#include <cuda_fp16.h>
#include <cstdint>

// ---------------- problem dims ----------------
static constexpr int BB   = 8192;
static constexpr int DD   = 1024;
static constexpr int HDIM = 1024;
static constexpr int KK   = 2048;   // 2*D  (x|h)
static constexpr int NN   = 4096;   // 4*H  (gate-interleaved: col = 4*h + gate)

// ---------------- GEMM tiling ----------------
static constexpr int BM = 128;
static constexpr int BN = 128;
static constexpr int BK = 64;                 // fp16 per K chunk = 128B row
static constexpr int K_ITERS = KK / BK;       // 32
static constexpr int STAGES  = 3;

static constexpr int A_STG = BM * 128;        // 16 KB
static constexpr int B_STG = BN * 128;        // 16 KB
static constexpr int STGB  = A_STG + B_STG;   // 32 KB
static constexpr int OFF_MBAR = STAGES * STGB;            // 98304
static constexpr int SMEM_DYN = OFF_MBAR + 64 + 1024;

// epilogue staging (float indices into smem, reusing stage buffers)
static constexpr int EPI_STRIDE = 36;                     // padded row stride (floats)
static constexpr int HSF  = 0;                            // h tile 128x32
static constexpr int CSF  = 128 * EPI_STRIDE;             // c tile
static constexpr int C1F  = 2 * 128 * EPI_STRIDE;         // c1 tile

// ---------------- scratch (static device arrays; no allocation) ----------------
__device__ __align__(1024) __half g_A[(size_t)BB * KK];   // 32 MB
__device__ __align__(1024) __half g_W[(size_t)NN * KK];   // 16 MB
__device__ float g_bias[NN];

// ---------------- PTX helpers ----------------
__device__ __forceinline__ uint32_t s2u(const void* p) {
    uint32_t a;
    asm("{ .reg .u64 t; cvta.to.shared.u64 t, %1; cvt.u32.u64 %0, t; }" : "=r"(a) : "l"(p));
    return a;
}
__device__ __forceinline__ void mbar_init(uint32_t a, uint32_t cnt) {
    asm volatile("mbarrier.init.shared.b64 [%0], %1;" :: "r"(a), "r"(cnt) : "memory");
}
__device__ __forceinline__ void mbar_expect_tx(uint32_t a, uint32_t bytes) {
    asm volatile("mbarrier.arrive.expect_tx.shared.b64 _, [%0], %1;" :: "r"(a), "r"(bytes) : "memory");
}
__device__ __forceinline__ void mbar_arrive(uint32_t a) {
    asm volatile("mbarrier.arrive.shared.b64 _, [%0];" :: "r"(a) : "memory");
}
__device__ __forceinline__ void mbar_wait(uint32_t a, uint32_t parity) {
    asm volatile(
        "{\n\t.reg .pred P;\n\t"
        "WL%=:\n\t"
        "mbarrier.try_wait.parity.acquire.cta.shared::cta.b64 P, [%0], %1, 0x989680;\n\t"
        "@P bra WD%=;\n\t"
        "bra WL%=;\n\t"
        "WD%=:\n\t}"
        :: "r"(a), "r"(parity) : "memory");
}
__device__ __forceinline__ void tma_2d(uint32_t dst, const CUtensorMap* map,
                                       int cx, int cy, uint32_t mbar) {
    asm volatile(
        "cp.async.bulk.tensor.2d.shared::cta.global.tile.mbarrier::complete_tx::bytes "
        "[%0], [%1, {%2, %3}], [%4];"
        :: "r"(dst), "l"(map), "r"(cx), "r"(cy), "r"(mbar) : "memory");
}
__device__ __forceinline__ void ldsm4(uint32_t (&r)[4], uint32_t a) {
    asm volatile("ldmatrix.sync.aligned.m8n8.x4.shared.b16 {%0,%1,%2,%3}, [%4];"
        : "=r"(r[0]), "=r"(r[1]), "=r"(r[2]), "=r"(r[3]) : "r"(a));
}
__device__ __forceinline__ void mma16816(float (&d)[4], const uint32_t (&a)[4],
                                         uint32_t b0, uint32_t b1) {
    asm volatile(
        "mma.sync.aligned.m16n8k16.row.col.f32.f16.f16.f32 "
        "{%0,%1,%2,%3}, {%4,%5,%6,%7}, {%8,%9}, {%0,%1,%2,%3};"
        : "+f"(d[0]), "+f"(d[1]), "+f"(d[2]), "+f"(d[3])
        : "r"(a[0]), "r"(a[1]), "r"(a[2]), "r"(a[3]), "r"(b0), "r"(b1));
}
__device__ __forceinline__ float4 ldcs4(const float* p) {
    float4 v;
    asm volatile("ld.global.cs.v4.f32 {%0,%1,%2,%3}, [%4];"
        : "=f"(v.x), "=f"(v.y), "=f"(v.z), "=f"(v.w) : "l"(p));
    return v;
}
__device__ __forceinline__ float sigf(float x) {
    return __fdividef(1.0f, 1.0f + __expf(-x));
}
__device__ __forceinline__ float tanh_acc(float x) {
    return __fmaf_rn(2.0f, sigf(2.0f * x), -1.0f);
}
__device__ __forceinline__ uint32_t packh2(float a, float b) {
    __half2 v = __floats2half2_rn(a, b);
    return *reinterpret_cast<uint32_t*>(&v);
}

// ---------------- merged prep kernel (R12 layout: 4x float4/thread, MLP=4) ----------------
// Single retained R13 variable: .cs (evict-first) on the single-touch fp32 reads.
static constexpr int PREP_A_BLOCKS = BB * (KK / 16) / 256;   // 4096
static constexpr int PREP_W_BLOCKS = NN * (KK / 16) / 256;   // 2048

__global__ void __launch_bounds__(256)
prep_all_kernel(const float* __restrict__ x, const float* __restrict__ h,
                const float* __restrict__ Wx, const float* __restrict__ bx,
                const float* __restrict__ Wh, const float* __restrict__ bh) {
    const int blk = blockIdx.x;
    const float* srcbase;
    __half* dst;
    if (blk < PREP_A_BLOCKS) {
        int gid = blk * 256 + threadIdx.x;      // over BB * (KK/16)
        int row = gid >> 7;                     // KK/16 = 128 segments/row
        int seg = gid & 127;
        int d0  = seg << 4;
        srcbase = (d0 < DD) ? (x + (size_t)row * DD + d0)
                            : (h + (size_t)row * DD + (d0 - DD));
        dst = g_A + (size_t)row * KK + d0;
    } else {
        int gid = (blk - PREP_A_BLOCKS) * 256 + threadIdx.x;   // over NN * (KK/16)
        int row = gid >> 7;
        int seg = gid & 127;
        int d0  = seg << 4;
        int gate = row & 3;
        int hh   = row >> 2;
        int old  = (gate << 10) + hh;           // gate*1024 + h
        srcbase = (d0 < DD) ? (Wx + (size_t)old * DD + d0)
                            : (Wh + (size_t)old * DD + (d0 - DD));
        dst = g_W + (size_t)row * KK + d0;
        if (seg == 0) g_bias[row] = bx[old] + bh[old];
    }
    float4 v0 = ldcs4(srcbase);
    float4 v1 = ldcs4(srcbase + 4);
    float4 v2 = ldcs4(srcbase + 8);
    float4 v3 = ldcs4(srcbase + 12);
    uint4 o0, o1;
    o0.x = packh2(v0.x, v0.y);
    o0.y = packh2(v0.z, v0.w);
    o0.z = packh2(v1.x, v1.y);
    o0.w = packh2(v1.z, v1.w);
    o1.x = packh2(v2.x, v2.y);
    o1.y = packh2(v2.z, v2.w);
    o1.z = packh2(v3.x, v3.y);
    o1.w = packh2(v3.z, v3.w);
    *reinterpret_cast<uint4*>(dst)     = o0;
    *reinterpret_cast<uint4*>(dst + 8) = o1;
}

// ---------------- fused GEMM + LSTM gate kernel (R12, byte-identical) ----------------
__global__ void __launch_bounds__(256, 2)
lstm_gemm_kernel(const __grid_constant__ CUtensorMap mapA,
                 const __grid_constant__ CUtensorMap mapB,
                 const float* __restrict__ c1_g,
                 float* __restrict__ h_out,
                 float* __restrict__ c_out) {
    extern __shared__ char smem_raw[];
    uint32_t s0   = s2u(smem_raw);
    uint32_t pad  = (1024u - (s0 & 1023u)) & 1023u;
    uint32_t sbase = s0 + pad;
    float* fbase = reinterpret_cast<float*>(smem_raw + pad);

    const int tid  = threadIdx.x;
    const int wid  = tid >> 5;
    const int lane = tid & 31;
    const int wm   = wid >> 1;            // 0..3 (m)
    const int wn   = wid & 1;             // 0..1 (n)
    const int m_base = blockIdx.y * BM;
    const int n_base = blockIdx.x * BN;
    const int h_base = blockIdx.x * (BN / 4);   // 32 h per tile

    const uint32_t FULL  = sbase + OFF_MBAR;          // full[s] : +8s
    const uint32_t EMPTY = sbase + OFF_MBAR + 8 * STAGES;

    if (tid == 0) {
        for (int s = 0; s < STAGES; s++) {
            mbar_init(FULL + 8 * s, 1);
            mbar_init(EMPTY + 8 * s, 8);   // one arrive per warp
        }
        asm volatile("fence.proxy.async.shared::cta;" ::: "memory");
    }
    __syncthreads();

    // prologue: fill stages 0,1
    if (tid == 0) {
        #pragma unroll
        for (int s = 0; s < STAGES - 1; s++) {
            mbar_expect_tx(FULL + 8 * s, (uint32_t)STGB);
            uint32_t dA = sbase + s * STGB;
            tma_2d(dA,         &mapA, s * BK, m_base, FULL + 8 * s);
            tma_2d(dA + A_STG, &mapB, s * BK, n_base, FULL + 8 * s);
        }
    }

    float acc[2][8][4];
    #pragma unroll
    for (int i = 0; i < 2; i++)
        #pragma unroll
        for (int j = 0; j < 8; j++)
            #pragma unroll
            for (int e = 0; e < 4; e++) acc[i][j][e] = 0.0f;

    const int lrow = lane & 15;     // ldmatrix row within 16
    const int lch  = lane >> 4;     // ldmatrix k half
    const int raA0 = wm * 32 + lrow;
    const int raA1 = raA0 + 16;
    const int rb0  = wn * 64 + lrow;

    // loop-invariant swizzled fragment offsets (stage-relative)
    const uint32_t offA0 = (uint32_t)(raA0 * 128) + (uint32_t)((lch ^ (raA0 & 7)) << 4);
    const uint32_t offA1 = (uint32_t)(raA1 * 128) + (uint32_t)((lch ^ (raA1 & 7)) << 4);
    uint32_t offB[4];
    #pragma unroll
    for (int nf2 = 0; nf2 < 4; nf2++) {
        int rb = rb0 + nf2 * 16;
        offB[nf2] = (uint32_t)A_STG + (uint32_t)(rb * 128)
                  + (uint32_t)((lch ^ (rb & 7)) << 4);
    }

    // fragment double buffers
    uint32_t a0b[2][4], a1b[2][4], bfb[2][4][4];

    int b = 0, phase = 0;   // consumer stage index / parity (incremental)

    for (int kb = 0; kb < K_ITERS; kb++) {
        // producer for stage kb+2 — rotating warp, BEFORE consuming FULL[b]
        if (wid == (kb & 7) && lane == 0) {
            int nf = kb + STAGES - 1;
            if (nf < K_ITERS) {
                int b2 = b + STAGES - 1;
                if (b2 >= STAGES) b2 -= STAGES;
                if (nf >= STAGES) {
                    mbar_wait(EMPTY + 8 * b2, ((nf - STAGES) / 3) & 1);
                }
                mbar_expect_tx(FULL + 8 * b2, (uint32_t)STGB);
                uint32_t dA = sbase + b2 * STGB;
                tma_2d(dA,         &mapA, nf * BK, m_base, FULL + 8 * b2);
                tma_2d(dA + A_STG, &mapB, nf * BK, n_base, FULL + 8 * b2);
            }
        }

        mbar_wait(FULL + 8 * b, phase);

        const uint32_t sA  = sbase + b * STGB;
        const uint32_t bA0 = sA + offA0;
        const uint32_t bA1 = sA + offA1;
        uint32_t bB[4];
        #pragma unroll
        for (int nf2 = 0; nf2 < 4; nf2++) bB[nf2] = sA + offB[nf2];

        // preload ks=0 fragments into buffer 0
        ldsm4(a0b[0], bA0);
        ldsm4(a1b[0], bA1);
        #pragma unroll
        for (int nf2 = 0; nf2 < 4; nf2++) ldsm4(bfb[0][nf2], bB[nf2]);

        #pragma unroll
        for (int ks = 0; ks < 4; ks++) {
            const int cur = ks & 1;
            if (ks < 3) {
                const uint32_t x5 = (uint32_t)((ks + 1) << 5);   // swizzle XOR step
                ldsm4(a0b[cur ^ 1], bA0 ^ x5);
                ldsm4(a1b[cur ^ 1], bA1 ^ x5);
                #pragma unroll
                for (int nf2 = 0; nf2 < 4; nf2++)
                    ldsm4(bfb[cur ^ 1][nf2], bB[nf2] ^ x5);
            }
            #pragma unroll
            for (int nf = 0; nf < 4; nf++) {
                mma16816(acc[0][2 * nf],     a0b[cur], bfb[cur][nf][0], bfb[cur][nf][2]);
                mma16816(acc[0][2 * nf + 1], a0b[cur], bfb[cur][nf][1], bfb[cur][nf][3]);
                mma16816(acc[1][2 * nf],     a1b[cur], bfb[cur][nf][0], bfb[cur][nf][2]);
                mma16816(acc[1][2 * nf + 1], a1b[cur], bfb[cur][nf][1], bfb[cur][nf][3]);
            }
        }
        if (lane == 0) mbar_arrive(EMPTY + 8 * b);

        if (++b == STAGES) { b = 0; phase ^= 1; }
    }

    // -------- epilogue (register-prefetched) --------
    const int t    = lane & 3;           // quad col pair: local cols 2t, 2t+1
    const int rowg = lane >> 2;
    const bool evenT = (t & 1) == 0;     // holds (gi, gf); odd holds (go, gc)

    // 1) prefetch c1 tile rows (coalesced) + per-thread bias into registers
    //    BEFORE the barrier — latency overlaps the straggler wait.
    float4 c1r[4];
    #pragma unroll
    for (int i = 0; i < 4; i++) {
        int idx = tid + i * 256;                 // 1024 = 128*8 float4 slots
        int row = idx >> 3;
        int q   = idx & 7;
        c1r[i] = *reinterpret_cast<const float4*>(
            c1_g + (size_t)(m_base + row) * HDIM + h_base + q * 4);
    }
    float2 biasr[8];
    #pragma unroll
    for (int nj = 0; nj < 8; nj++) {
        biasr[nj] = *reinterpret_cast<const float2*>(
            g_bias + n_base + wn * 64 + nj * 8 + 2 * t);
    }

    __syncthreads();   // mainloop done -> stage buffers reusable

    // 2) spill prefetched c1 to smem (shared-layout exchange)
    #pragma unroll
    for (int i = 0; i < 4; i++) {
        int idx = tid + i * 256;
        int row = idx >> 3;
        int q   = idx & 7;
        *reinterpret_cast<float4*>(fbase + C1F + row * EPI_STRIDE + q * 4) = c1r[i];
    }
    __syncthreads();

    #pragma unroll
    for (int mf = 0; mf < 2; mf++) {
        const int rl0 = wm * 32 + mf * 16 + rowg;   // local row
        const int rl1 = rl0 + 8;
        #pragma unroll
        for (int nj = 0; nj < 8; nj++) {
            const float2 bias = biasr[nj];
            float g0a = acc[mf][nj][0] + bias.x;
            float g1a = acc[mf][nj][1] + bias.y;
            float g0b = acc[mf][nj][2] + bias.x;
            float g1b = acc[mf][nj][3] + bias.y;

            float pa = sigf(g0a);
            float qa = evenT ? sigf(g1a) : tanh_acc(g1a);
            float pb = sigf(g0b);
            float qb = evenT ? sigf(g1b) : tanh_acc(g1b);

            float ov_a = __shfl_xor_sync(0xFFFFFFFFu, pa, 1);
            float ct_a = __shfl_xor_sync(0xFFFFFFFFu, qa, 1);
            float ov_b = __shfl_xor_sync(0xFFFFFFFFu, pb, 1);
            float ct_b = __shfl_xor_sync(0xFFFFFFFFu, qb, 1);

            const int hl = wn * 16 + nj * 2 + (t >> 1);
            float cna = 0.f, cnb = 0.f, hna = 0.f, hnb = 0.f;
            if (evenT) {
                float c1a = fbase[C1F + rl0 * EPI_STRIDE + hl];
                float c1b = fbase[C1F + rl1 * EPI_STRIDE + hl];
                cna = sigf(qa * c1a + pa * ct_a);
                cnb = sigf(qb * c1b + pb * ct_b);
                hna = tanh_acc(cna) * ov_a;
                hnb = tanh_acc(cnb) * ov_b;
            }
            float cna2 = __shfl_xor_sync(0xFFFFFFFFu, cna, 2);
            float cnb2 = __shfl_xor_sync(0xFFFFFFFFu, cnb, 2);
            float hna2 = __shfl_xor_sync(0xFFFFFFFFu, hna, 2);
            float hnb2 = __shfl_xor_sync(0xFFFFFFFFu, hnb, 2);
            if (t == 0) {
                const int c2 = wn * 16 + nj * 2;
                *reinterpret_cast<float2*>(fbase + HSF + rl0 * EPI_STRIDE + c2) =
                    make_float2(hna, hna2);
                *reinterpret_cast<float2*>(fbase + HSF + rl1 * EPI_STRIDE + c2) =
                    make_float2(hnb, hnb2);
                *reinterpret_cast<float2*>(fbase + CSF + rl0 * EPI_STRIDE + c2) =
                    make_float2(cna, cna2);
                *reinterpret_cast<float2*>(fbase + CSF + rl1 * EPI_STRIDE + c2) =
                    make_float2(cnb, cnb2);
            }
        }
    }
    __syncthreads();

    // coalesced global stores
    for (int idx = tid; idx < 128 * 8; idx += 256) {
        int row = idx >> 3;
        int q   = idx & 7;
        float4 hv = *reinterpret_cast<const float4*>(fbase + HSF + row * EPI_STRIDE + q * 4);
        float4 cv = *reinterpret_cast<const float4*>(fbase + CSF + row * EPI_STRIDE + q * 4);
        size_t off = (size_t)(m_base + row) * HDIM + h_base + q * 4;
        *reinterpret_cast<float4*>(h_out + off) = hv;
        *reinterpret_cast<float4*>(c_out + off) = cv;
    }
}

// ---------------- host launcher ----------------
typedef CUresult (*tme_fn_t)(CUtensorMap*, CUtensorMapDataType, cuuint32_t, void*,
                             const cuuint64_t*, const cuuint64_t*, const cuuint32_t*,
                             const cuuint32_t*, CUtensorMapInterleave, CUtensorMapSwizzle,
                             CUtensorMapL2promotion, CUtensorMapFloatOOBfill);

static tme_fn_t get_encoder() {
    void* fn = nullptr;
    cudaDriverEntryPointQueryResult qr;
#if CUDART_VERSION >= 12050
    cudaGetDriverEntryPointByVersion("cuTensorMapEncodeTiled", &fn, 12000,
                                     cudaEnableDefault, &qr);
#else
    cudaGetDriverEntryPoint("cuTensorMapEncodeTiled", &fn, cudaEnableDefault, &qr);
#endif
    return (tme_fn_t)fn;
}

extern "C" void kernel_launch(void* const* d_in, const int* in_sizes, int n_in,
                              void* d_out, int out_size) {
    const float* x  = (const float*)d_in[0];
    const float* h  = (const float*)d_in[1];
    const float* c1 = (const float*)d_in[2];
    const float* Wx = (const float*)d_in[3];
    const float* bx = (const float*)d_in[4];
    const float* Wh = (const float*)d_in[5];
    const float* bh = (const float*)d_in[6];
    float* h_out = (float*)d_out;
    float* c_out = h_out + (size_t)BB * HDIM;

    prep_all_kernel<<<PREP_A_BLOCKS + PREP_W_BLOCKS, 256>>>(x, h, Wx, bx, Wh, bh);

    void* aptr = nullptr; void* wptr = nullptr;
    cudaGetSymbolAddress(&aptr, g_A);
    cudaGetSymbolAddress(&wptr, g_W);
    tme_fn_t enc = get_encoder();
    if (!enc) return;

    CUtensorMap mapA, mapB;
    cuuint64_t dimsA[2] = {(cuuint64_t)KK, (cuuint64_t)BB};
    cuuint64_t strA[1]  = {(cuuint64_t)KK * 2};
    cuuint32_t boxA[2]  = {BK, BM};
    cuuint32_t es[2]    = {1, 1};
    enc(&mapA, CU_TENSOR_MAP_DATA_TYPE_FLOAT16, 2, aptr, dimsA, strA, boxA, es,
        CU_TENSOR_MAP_INTERLEAVE_NONE, CU_TENSOR_MAP_SWIZZLE_128B,
        CU_TENSOR_MAP_L2_PROMOTION_L2_128B, CU_TENSOR_MAP_FLOAT_OOB_FILL_NONE);

    cuuint64_t dimsB[2] = {(cuuint64_t)KK, (cuuint64_t)NN};
    cuuint32_t boxB[2]  = {BK, BN};
    enc(&mapB, CU_TENSOR_MAP_DATA_TYPE_FLOAT16, 2, wptr, dimsB, strA, boxB, es,
        CU_TENSOR_MAP_INTERLEAVE_NONE, CU_TENSOR_MAP_SWIZZLE_128B,
        CU_TENSOR_MAP_L2_PROMOTION_L2_128B, CU_TENSOR_MAP_FLOAT_OOB_FILL_NONE);

    cudaFuncSetAttribute(lstm_gemm_kernel,
                         cudaFuncAttributeMaxDynamicSharedMemorySize, SMEM_DYN);
    dim3 grid(NN / BN, BB / BM);   // (32, 64)
    lstm_gemm_kernel<<<grid, 256, SMEM_DYN>>>(mapA, mapB, c1, h_out, c_out);
}

// round 15
// speedup vs baseline: 1.0362x; 1.0015x over previous
#include <cuda_runtime.h>
#include <cuda.h>
#include <cuda_fp16.h>
#include <cstdint>

// ---------------- problem dims ----------------
static constexpr int BB   = 8192;
static constexpr int DD   = 1024;
static constexpr int HDIM = 1024;
static constexpr int KK   = 2048;   // 2*D  (x|h)
static constexpr int NN   = 4096;   // 4*H  (gate-interleaved: col = 4*h + gate)

// ---------------- GEMM tiling ----------------
static constexpr int BM = 128;
static constexpr int BN = 128;
static constexpr int BK = 64;                 // fp16 per K chunk = 128B row
static constexpr int K_ITERS = KK / BK;       // 32
static constexpr int STAGES  = 3;

static constexpr int A_STG = BM * 128;        // 16 KB
static constexpr int B_STG = BN * 128;        // 16 KB
static constexpr int STGB  = A_STG + B_STG;   // 32 KB
static constexpr int OFF_MBAR = STAGES * STGB;            // 98304
static constexpr int SMEM_DYN = OFF_MBAR + 64 + 1024;

// epilogue staging (float indices into smem, reusing stage buffers)
static constexpr int EPI_STRIDE = 36;                     // padded row stride (floats)
static constexpr int HSF  = 0;                            // h tile 128x32
static constexpr int CSF  = 128 * EPI_STRIDE;             // c tile
static constexpr int C1F  = 2 * 128 * EPI_STRIDE;         // c1 tile

// ---------------- scratch (static device arrays; no allocation) ----------------
__device__ __align__(1024) __half g_A[(size_t)BB * KK];   // 32 MB
__device__ __align__(1024) __half g_W[(size_t)NN * KK];   // 16 MB
__device__ float g_bias[NN];

// ---------------- PTX helpers ----------------
__device__ __forceinline__ uint32_t s2u(const void* p) {
    uint32_t a;
    asm("{ .reg .u64 t; cvta.to.shared.u64 t, %1; cvt.u32.u64 %0, t; }" : "=r"(a) : "l"(p));
    return a;
}
__device__ __forceinline__ void mbar_init(uint32_t a, uint32_t cnt) {
    asm volatile("mbarrier.init.shared.b64 [%0], %1;" :: "r"(a), "r"(cnt) : "memory");
}
__device__ __forceinline__ void mbar_expect_tx(uint32_t a, uint32_t bytes) {
    asm volatile("mbarrier.arrive.expect_tx.shared.b64 _, [%0], %1;" :: "r"(a), "r"(bytes) : "memory");
}
__device__ __forceinline__ void mbar_arrive(uint32_t a) {
    asm volatile("mbarrier.arrive.shared.b64 _, [%0];" :: "r"(a) : "memory");
}
__device__ __forceinline__ void mbar_wait(uint32_t a, uint32_t parity) {
    asm volatile(
        "{\n\t.reg .pred P;\n\t"
        "WL%=:\n\t"
        "mbarrier.try_wait.parity.acquire.cta.shared::cta.b64 P, [%0], %1, 0x989680;\n\t"
        "@P bra WD%=;\n\t"
        "bra WL%=;\n\t"
        "WD%=:\n\t}"
        :: "r"(a), "r"(parity) : "memory");
}
__device__ __forceinline__ void tma_2d(uint32_t dst, const CUtensorMap* map,
                                       int cx, int cy, uint32_t mbar) {
    asm volatile(
        "cp.async.bulk.tensor.2d.shared::cta.global.tile.mbarrier::complete_tx::bytes "
        "[%0], [%1, {%2, %3}], [%4];"
        :: "r"(dst), "l"(map), "r"(cx), "r"(cy), "r"(mbar) : "memory");
}
__device__ __forceinline__ void ldsm4(uint32_t (&r)[4], uint32_t a) {
    asm volatile("ldmatrix.sync.aligned.m8n8.x4.shared.b16 {%0,%1,%2,%3}, [%4];"
        : "=r"(r[0]), "=r"(r[1]), "=r"(r[2]), "=r"(r[3]) : "r"(a));
}
__device__ __forceinline__ void mma16816(float (&d)[4], const uint32_t (&a)[4],
                                         uint32_t b0, uint32_t b1) {
    asm volatile(
        "mma.sync.aligned.m16n8k16.row.col.f32.f16.f16.f32 "
        "{%0,%1,%2,%3}, {%4,%5,%6,%7}, {%8,%9}, {%0,%1,%2,%3};"
        : "+f"(d[0]), "+f"(d[1]), "+f"(d[2]), "+f"(d[3])
        : "r"(a[0]), "r"(a[1]), "r"(a[2]), "r"(a[3]), "r"(b0), "r"(b1));
}
__device__ __forceinline__ float4 ldcs4(const float* p) {
    float4 v;
    asm volatile("ld.global.cs.v4.f32 {%0,%1,%2,%3}, [%4];"
        : "=f"(v.x), "=f"(v.y), "=f"(v.z), "=f"(v.w) : "l"(p));
    return v;
}
__device__ __forceinline__ float sigf(float x) {
    return __fdividef(1.0f, 1.0f + __expf(-x));
}
__device__ __forceinline__ float tanh_acc(float x) {
    return __fmaf_rn(2.0f, sigf(2.0f * x), -1.0f);
}
__device__ __forceinline__ uint32_t packh2(float a, float b) {
    __half2 v = __floats2half2_rn(a, b);
    return *reinterpret_cast<uint32_t*>(&v);
}

// ---------------- merged prep kernel (R14: 4x float4/thread, MLP=4, .cs) ----------------
static constexpr int PREP_A_BLOCKS = BB * (KK / 16) / 256;   // 4096
static constexpr int PREP_W_BLOCKS = NN * (KK / 16) / 256;   // 2048

__global__ void __launch_bounds__(256)
prep_all_kernel(const float* __restrict__ x, const float* __restrict__ h,
                const float* __restrict__ Wx, const float* __restrict__ bx,
                const float* __restrict__ Wh, const float* __restrict__ bh) {
#if __CUDA_ARCH__ >= 900
    // Fire PDL trigger early: the dependent GEMM grid may begin launching and
    // run its prologue concurrently; its gridsync still waits for our completion.
    cudaTriggerProgrammaticLaunchCompletion();
#endif
    const int blk = blockIdx.x;
    const float* srcbase;
    __half* dst;
    if (blk < PREP_A_BLOCKS) {
        int gid = blk * 256 + threadIdx.x;      // over BB * (KK/16)
        int row = gid >> 7;                     // KK/16 = 128 segments/row
        int seg = gid & 127;
        int d0  = seg << 4;
        srcbase = (d0 < DD) ? (x + (size_t)row * DD + d0)
                            : (h + (size_t)row * DD + (d0 - DD));
        dst = g_A + (size_t)row * KK + d0;
    } else {
        int gid = (blk - PREP_A_BLOCKS) * 256 + threadIdx.x;   // over NN * (KK/16)
        int row = gid >> 7;
        int seg = gid & 127;
        int d0  = seg << 4;
        int gate = row & 3;
        int hh   = row >> 2;
        int old  = (gate << 10) + hh;           // gate*1024 + h
        srcbase = (d0 < DD) ? (Wx + (size_t)old * DD + d0)
                            : (Wh + (size_t)old * DD + (d0 - DD));
        dst = g_W + (size_t)row * KK + d0;
        if (seg == 0) g_bias[row] = bx[old] + bh[old];
    }
    float4 v0 = ldcs4(srcbase);
    float4 v1 = ldcs4(srcbase + 4);
    float4 v2 = ldcs4(srcbase + 8);
    float4 v3 = ldcs4(srcbase + 12);
    uint4 o0, o1;
    o0.x = packh2(v0.x, v0.y);
    o0.y = packh2(v0.z, v0.w);
    o0.z = packh2(v1.x, v1.y);
    o0.w = packh2(v1.z, v1.w);
    o1.x = packh2(v2.x, v2.y);
    o1.y = packh2(v2.z, v2.w);
    o1.z = packh2(v3.x, v3.y);
    o1.w = packh2(v3.z, v3.w);
    *reinterpret_cast<uint4*>(dst)     = o0;
    *reinterpret_cast<uint4*>(dst + 8) = o1;
}

// ---------------- fused GEMM + LSTM gate kernel (R14 + PDL gridsync) ----------------
__global__ void __launch_bounds__(256, 2)
lstm_gemm_kernel(const __grid_constant__ CUtensorMap mapA,
                 const __grid_constant__ CUtensorMap mapB,
                 const float* __restrict__ c1_g,
                 float* __restrict__ h_out,
                 float* __restrict__ c_out) {
    extern __shared__ char smem_raw[];
    uint32_t s0   = s2u(smem_raw);
    uint32_t pad  = (1024u - (s0 & 1023u)) & 1023u;
    uint32_t sbase = s0 + pad;
    float* fbase = reinterpret_cast<float*>(smem_raw + pad);

    const int tid  = threadIdx.x;
    const int wid  = tid >> 5;
    const int lane = tid & 31;
    const int wm   = wid >> 1;            // 0..3 (m)
    const int wn   = wid & 1;             // 0..1 (n)
    const int m_base = blockIdx.y * BM;
    const int n_base = blockIdx.x * BN;
    const int h_base = blockIdx.x * (BN / 4);   // 32 h per tile

    const uint32_t FULL  = sbase + OFF_MBAR;          // full[s] : +8s
    const uint32_t EMPTY = sbase + OFF_MBAR + 8 * STAGES;

    if (tid == 0) {
        for (int s = 0; s < STAGES; s++) {
            mbar_init(FULL + 8 * s, 1);
            mbar_init(EMPTY + 8 * s, 8);   // one arrive per warp
        }
        asm volatile("fence.proxy.async.shared::cta;" ::: "memory");
    }
    __syncthreads();

    // prologue computed offsets (no data consumption yet)
    float acc[2][8][4];
    #pragma unroll
    for (int i = 0; i < 2; i++)
        #pragma unroll
        for (int j = 0; j < 8; j++)
            #pragma unroll
            for (int e = 0; e < 4; e++) acc[i][j][e] = 0.0f;

    const int lrow = lane & 15;     // ldmatrix row within 16
    const int lch  = lane >> 4;     // ldmatrix k half
    const int raA0 = wm * 32 + lrow;
    const int raA1 = raA0 + 16;
    const int rb0  = wn * 64 + lrow;

    const uint32_t offA0 = (uint32_t)(raA0 * 128) + (uint32_t)((lch ^ (raA0 & 7)) << 4);
    const uint32_t offA1 = (uint32_t)(raA1 * 128) + (uint32_t)((lch ^ (raA1 & 7)) << 4);
    uint32_t offB[4];
    #pragma unroll
    for (int nf2 = 0; nf2 < 4; nf2++) {
        int rb = rb0 + nf2 * 16;
        offB[nf2] = (uint32_t)A_STG + (uint32_t)(rb * 128)
                  + (uint32_t)((lch ^ (rb & 7)) << 4);
    }

#if __CUDA_ARCH__ >= 900
    // PDL: wait for prep grid to fully complete before consuming g_A/g_W/g_bias.
    cudaGridDependencySynchronize();
#endif

    // prologue: fill stages 0,1 (first data consumption — after gridsync)
    if (tid == 0) {
        #pragma unroll
        for (int s = 0; s < STAGES - 1; s++) {
            mbar_expect_tx(FULL + 8 * s, (uint32_t)STGB);
            uint32_t dA = sbase + s * STGB;
            tma_2d(dA,         &mapA, s * BK, m_base, FULL + 8 * s);
            tma_2d(dA + A_STG, &mapB, s * BK, n_base, FULL + 8 * s);
        }
    }

    // fragment double buffers
    uint32_t a0b[2][4], a1b[2][4], bfb[2][4][4];

    int b = 0, phase = 0;   // consumer stage index / parity (incremental)

    for (int kb = 0; kb < K_ITERS; kb++) {
        // producer for stage kb+2 — rotating warp, BEFORE consuming FULL[b]
        if (wid == (kb & 7) && lane == 0) {
            int nf = kb + STAGES - 1;
            if (nf < K_ITERS) {
                int b2 = b + STAGES - 1;
                if (b2 >= STAGES) b2 -= STAGES;
                if (nf >= STAGES) {
                    mbar_wait(EMPTY + 8 * b2, ((nf - STAGES) / 3) & 1);
                }
                mbar_expect_tx(FULL + 8 * b2, (uint32_t)STGB);
                uint32_t dA = sbase + b2 * STGB;
                tma_2d(dA,         &mapA, nf * BK, m_base, FULL + 8 * b2);
                tma_2d(dA + A_STG, &mapB, nf * BK, n_base, FULL + 8 * b2);
            }
        }

        mbar_wait(FULL + 8 * b, phase);

        const uint32_t sA  = sbase + b * STGB;
        const uint32_t bA0 = sA + offA0;
        const uint32_t bA1 = sA + offA1;
        uint32_t bB[4];
        #pragma unroll
        for (int nf2 = 0; nf2 < 4; nf2++) bB[nf2] = sA + offB[nf2];

        // preload ks=0 fragments into buffer 0
        ldsm4(a0b[0], bA0);
        ldsm4(a1b[0], bA1);
        #pragma unroll
        for (int nf2 = 0; nf2 < 4; nf2++) ldsm4(bfb[0][nf2], bB[nf2]);

        #pragma unroll
        for (int ks = 0; ks < 4; ks++) {
            const int cur = ks & 1;
            if (ks < 3) {
                const uint32_t x5 = (uint32_t)((ks + 1) << 5);   // swizzle XOR step
                ldsm4(a0b[cur ^ 1], bA0 ^ x5);
                ldsm4(a1b[cur ^ 1], bA1 ^ x5);
                #pragma unroll
                for (int nf2 = 0; nf2 < 4; nf2++)
                    ldsm4(bfb[cur ^ 1][nf2], bB[nf2] ^ x5);
            }
            #pragma unroll
            for (int nf = 0; nf < 4; nf++) {
                mma16816(acc[0][2 * nf],     a0b[cur], bfb[cur][nf][0], bfb[cur][nf][2]);
                mma16816(acc[0][2 * nf + 1], a0b[cur], bfb[cur][nf][1], bfb[cur][nf][3]);
                mma16816(acc[1][2 * nf],     a1b[cur], bfb[cur][nf][0], bfb[cur][nf][2]);
                mma16816(acc[1][2 * nf + 1], a1b[cur], bfb[cur][nf][1], bfb[cur][nf][3]);
            }
        }
        if (lane == 0) mbar_arrive(EMPTY + 8 * b);

        if (++b == STAGES) { b = 0; phase ^= 1; }
    }

    // -------- epilogue (register-prefetched) --------
    const int t    = lane & 3;           // quad col pair: local cols 2t, 2t+1
    const int rowg = lane >> 2;
    const bool evenT = (t & 1) == 0;     // holds (gi, gf); odd holds (go, gc)

    // 1) prefetch c1 tile rows (coalesced) + per-thread bias into registers
    //    BEFORE the barrier — latency overlaps the straggler wait.
    float4 c1r[4];
    #pragma unroll
    for (int i = 0; i < 4; i++) {
        int idx = tid + i * 256;                 // 1024 = 128*8 float4 slots
        int row = idx >> 3;
        int q   = idx & 7;
        c1r[i] = *reinterpret_cast<const float4*>(
            c1_g + (size_t)(m_base + row) * HDIM + h_base + q * 4);
    }
    float2 biasr[8];
    #pragma unroll
    for (int nj = 0; nj < 8; nj++) {
        biasr[nj] = *reinterpret_cast<const float2*>(
            g_bias + n_base + wn * 64 + nj * 8 + 2 * t);
    }

    __syncthreads();   // mainloop done -> stage buffers reusable

    // 2) spill prefetched c1 to smem (shared-layout exchange)
    #pragma unroll
    for (int i = 0; i < 4; i++) {
        int idx = tid + i * 256;
        int row = idx >> 3;
        int q   = idx & 7;
        *reinterpret_cast<float4*>(fbase + C1F + row * EPI_STRIDE + q * 4) = c1r[i];
    }
    __syncthreads();

    #pragma unroll
    for (int mf = 0; mf < 2; mf++) {
        const int rl0 = wm * 32 + mf * 16 + rowg;   // local row
        const int rl1 = rl0 + 8;
        #pragma unroll
        for (int nj = 0; nj < 8; nj++) {
            const float2 bias = biasr[nj];
            float g0a = acc[mf][nj][0] + bias.x;
            float g1a = acc[mf][nj][1] + bias.y;
            float g0b = acc[mf][nj][2] + bias.x;
            float g1b = acc[mf][nj][3] + bias.y;

            float pa = sigf(g0a);
            float qa = evenT ? sigf(g1a) : tanh_acc(g1a);
            float pb = sigf(g0b);
            float qb = evenT ? sigf(g1b) : tanh_acc(g1b);

            float ov_a = __shfl_xor_sync(0xFFFFFFFFu, pa, 1);
            float ct_a = __shfl_xor_sync(0xFFFFFFFFu, qa, 1);
            float ov_b = __shfl_xor_sync(0xFFFFFFFFu, pb, 1);
            float ct_b = __shfl_xor_sync(0xFFFFFFFFu, qb, 1);

            const int hl = wn * 16 + nj * 2 + (t >> 1);
            float cna = 0.f, cnb = 0.f, hna = 0.f, hnb = 0.f;
            if (evenT) {
                float c1a = fbase[C1F + rl0 * EPI_STRIDE + hl];
                float c1b = fbase[C1F + rl1 * EPI_STRIDE + hl];
                cna = sigf(qa * c1a + pa * ct_a);
                cnb = sigf(qb * c1b + pb * ct_b);
                hna = tanh_acc(cna) * ov_a;
                hnb = tanh_acc(cnb) * ov_b;
            }
            float cna2 = __shfl_xor_sync(0xFFFFFFFFu, cna, 2);
            float cnb2 = __shfl_xor_sync(0xFFFFFFFFu, cnb, 2);
            float hna2 = __shfl_xor_sync(0xFFFFFFFFu, hna, 2);
            float hnb2 = __shfl_xor_sync(0xFFFFFFFFu, hnb, 2);
            if (t == 0) {
                const int c2 = wn * 16 + nj * 2;
                *reinterpret_cast<float2*>(fbase + HSF + rl0 * EPI_STRIDE + c2) =
                    make_float2(hna, hna2);
                *reinterpret_cast<float2*>(fbase + HSF + rl1 * EPI_STRIDE + c2) =
                    make_float2(hnb, hnb2);
                *reinterpret_cast<float2*>(fbase + CSF + rl0 * EPI_STRIDE + c2) =
                    make_float2(cna, cna2);
                *reinterpret_cast<float2*>(fbase + CSF + rl1 * EPI_STRIDE + c2) =
                    make_float2(cnb, cnb2);
            }
        }
    }
    __syncthreads();

    // coalesced global stores
    for (int idx = tid; idx < 128 * 8; idx += 256) {
        int row = idx >> 3;
        int q   = idx & 7;
        float4 hv = *reinterpret_cast<const float4*>(fbase + HSF + row * EPI_STRIDE + q * 4);
        float4 cv = *reinterpret_cast<const float4*>(fbase + CSF + row * EPI_STRIDE + q * 4);
        size_t off = (size_t)(m_base + row) * HDIM + h_base + q * 4;
        *reinterpret_cast<float4*>(h_out + off) = hv;
        *reinterpret_cast<float4*>(c_out + off) = cv;
    }
}

// ---------------- host launcher ----------------
typedef CUresult (*tme_fn_t)(CUtensorMap*, CUtensorMapDataType, cuuint32_t, void*,
                             const cuuint64_t*, const cuuint64_t*, const cuuint32_t*,
                             const cuuint32_t*, CUtensorMapInterleave, CUtensorMapSwizzle,
                             CUtensorMapL2promotion, CUtensorMapFloatOOBfill);

static tme_fn_t get_encoder() {
    void* fn = nullptr;
    cudaDriverEntryPointQueryResult qr;
#if CUDART_VERSION >= 12050
    cudaGetDriverEntryPointByVersion("cuTensorMapEncodeTiled", &fn, 12000,
                                     cudaEnableDefault, &qr);
#else
    cudaGetDriverEntryPoint("cuTensorMapEncodeTiled", &fn, cudaEnableDefault, &qr);
#endif
    return (tme_fn_t)fn;
}

extern "C" void kernel_launch(void* const* d_in, const int* in_sizes, int n_in,
                              void* d_out, int out_size) {
    const float* x  = (const float*)d_in[0];
    const float* h  = (const float*)d_in[1];
    const float* c1 = (const float*)d_in[2];
    const float* Wx = (const float*)d_in[3];
    const float* bx = (const float*)d_in[4];
    const float* Wh = (const float*)d_in[5];
    const float* bh = (const float*)d_in[6];
    float* h_out = (float*)d_out;
    float* c_out = h_out + (size_t)BB * HDIM;

    prep_all_kernel<<<PREP_A_BLOCKS + PREP_W_BLOCKS, 256>>>(x, h, Wx, bx, Wh, bh);

    void* aptr = nullptr; void* wptr = nullptr;
    cudaGetSymbolAddress(&aptr, g_A);
    cudaGetSymbolAddress(&wptr, g_W);
    tme_fn_t enc = get_encoder();
    if (!enc) return;

    CUtensorMap mapA, mapB;
    cuuint64_t dimsA[2] = {(cuuint64_t)KK, (cuuint64_t)BB};
    cuuint64_t strA[1]  = {(cuuint64_t)KK * 2};
    cuuint32_t boxA[2]  = {BK, BM};
    cuuint32_t es[2]    = {1, 1};
    enc(&mapA, CU_TENSOR_MAP_DATA_TYPE_FLOAT16, 2, aptr, dimsA, strA, boxA, es,
        CU_TENSOR_MAP_INTERLEAVE_NONE, CU_TENSOR_MAP_SWIZZLE_128B,
        CU_TENSOR_MAP_L2_PROMOTION_L2_128B, CU_TENSOR_MAP_FLOAT_OOB_FILL_NONE);

    cuuint64_t dimsB[2] = {(cuuint64_t)KK, (cuuint64_t)NN};
    cuuint32_t boxB[2]  = {BK, BN};
    enc(&mapB, CU_TENSOR_MAP_DATA_TYPE_FLOAT16, 2, wptr, dimsB, strA, boxB, es,
        CU_TENSOR_MAP_INTERLEAVE_NONE, CU_TENSOR_MAP_SWIZZLE_128B,
        CU_TENSOR_MAP_L2_PROMOTION_L2_128B, CU_TENSOR_MAP_FLOAT_OOB_FILL_NONE);

    cudaFuncSetAttribute(lstm_gemm_kernel,
                         cudaFuncAttributeMaxDynamicSharedMemorySize, SMEM_DYN);

    // PDL launch: GEMM may begin (prologue) while prep drains; gridsync inside
    // the kernel enforces the data dependency.
    cudaLaunchConfig_t cfg = {};
    cfg.gridDim  = dim3(NN / BN, BB / BM, 1);   // (32, 64)
    cfg.blockDim = dim3(256, 1, 1);
    cfg.dynamicSmemBytes = SMEM_DYN;
    cfg.stream = 0;
    cudaLaunchAttribute attrs[1];
    attrs[0].id = cudaLaunchAttributeProgrammaticStreamSerialization;
    attrs[0].val.programmaticStreamSerializationAllowed = 1;
    cfg.attrs = attrs;
    cfg.numAttrs = 1;
    cudaError_t err = cudaLaunchKernelEx(&cfg, lstm_gemm_kernel,
                                         mapA, mapB, c1, h_out, c_out);
    if (err != cudaSuccess) {
        // fallback: plain launch (no PDL)
        lstm_gemm_kernel<<<dim3(NN / BN, BB / BM), 256, SMEM_DYN>>>(
            mapA, mapB, c1, h_out, c_out);
    }
}

// round 16
// speedup vs baseline: 1.0397x; 1.0034x over previous
#include <cuda_runtime.h>
#include <cuda.h>
#include <cuda_fp16.h>
#include <cstdint>

// ---------------- problem dims ----------------
static constexpr int BB   = 8192;
static constexpr int DD   = 1024;
static constexpr int HDIM = 1024;
static constexpr int KK   = 2048;   // 2*D  (x|h)
static constexpr int NN   = 4096;   // 4*H  (gate-interleaved: col = 4*h + gate)

// ---------------- GEMM tiling ----------------
static constexpr int BM = 128;
static constexpr int BN = 128;
static constexpr int BK = 64;                 // fp16 per K chunk = 128B row
static constexpr int K_ITERS = KK / BK;       // 32
static constexpr int STAGES  = 3;

static constexpr int A_STG = BM * 128;        // 16 KB
static constexpr int B_STG = BN * 128;        // 16 KB
static constexpr int STGB  = A_STG + B_STG;   // 32 KB
static constexpr int OFF_MBAR = STAGES * STGB;            // 98304
static constexpr int SMEM_DYN = OFF_MBAR + 64 + 1024;

// epilogue staging (float indices into smem, reusing stage buffers)
static constexpr int EPI_STRIDE = 36;                     // padded row stride (floats)
static constexpr int HSF  = 0;                            // h tile 128x32
static constexpr int CSF  = 128 * EPI_STRIDE;             // c tile
static constexpr int C1F  = 2 * 128 * EPI_STRIDE;         // c1 tile

// ---------------- scratch (static device arrays; no allocation) ----------------
__device__ __align__(1024) __half g_A[(size_t)BB * KK];   // 32 MB
__device__ __align__(1024) __half g_W[(size_t)NN * KK];   // 16 MB
__device__ float g_bias[NN];

// ---------------- PTX helpers ----------------
__device__ __forceinline__ uint32_t s2u(const void* p) {
    uint32_t a;
    asm("{ .reg .u64 t; cvta.to.shared.u64 t, %1; cvt.u32.u64 %0, t; }" : "=r"(a) : "l"(p));
    return a;
}
__device__ __forceinline__ void mbar_init(uint32_t a, uint32_t cnt) {
    asm volatile("mbarrier.init.shared.b64 [%0], %1;" :: "r"(a), "r"(cnt) : "memory");
}
__device__ __forceinline__ void mbar_expect_tx(uint32_t a, uint32_t bytes) {
    asm volatile("mbarrier.arrive.expect_tx.shared.b64 _, [%0], %1;" :: "r"(a), "r"(bytes) : "memory");
}
__device__ __forceinline__ void mbar_arrive(uint32_t a) {
    asm volatile("mbarrier.arrive.shared.b64 _, [%0];" :: "r"(a) : "memory");
}
__device__ __forceinline__ void mbar_wait(uint32_t a, uint32_t parity) {
    asm volatile(
        "{\n\t.reg .pred P;\n\t"
        "WL%=:\n\t"
        "mbarrier.try_wait.parity.acquire.cta.shared::cta.b64 P, [%0], %1, 0x989680;\n\t"
        "@P bra WD%=;\n\t"
        "bra WL%=;\n\t"
        "WD%=:\n\t}"
        :: "r"(a), "r"(parity) : "memory");
}
__device__ __forceinline__ void tma_2d(uint32_t dst, const CUtensorMap* map,
                                       int cx, int cy, uint32_t mbar) {
    asm volatile(
        "cp.async.bulk.tensor.2d.shared::cta.global.tile.mbarrier::complete_tx::bytes "
        "[%0], [%1, {%2, %3}], [%4];"
        :: "r"(dst), "l"(map), "r"(cx), "r"(cy), "r"(mbar) : "memory");
}
__device__ __forceinline__ void ldsm4(uint32_t (&r)[4], uint32_t a) {
    asm volatile("ldmatrix.sync.aligned.m8n8.x4.shared.b16 {%0,%1,%2,%3}, [%4];"
        : "=r"(r[0]), "=r"(r[1]), "=r"(r[2]), "=r"(r[3]) : "r"(a));
}
__device__ __forceinline__ void mma16816(float (&d)[4], const uint32_t (&a)[4],
                                         uint32_t b0, uint32_t b1) {
    asm volatile(
        "mma.sync.aligned.m16n8k16.row.col.f32.f16.f16.f32 "
        "{%0,%1,%2,%3}, {%4,%5,%6,%7}, {%8,%9}, {%0,%1,%2,%3};"
        : "+f"(d[0]), "+f"(d[1]), "+f"(d[2]), "+f"(d[3])
        : "r"(a[0]), "r"(a[1]), "r"(a[2]), "r"(a[3]), "r"(b0), "r"(b1));
}
__device__ __forceinline__ float4 ldcs4(const float* p) {
    float4 v;
    asm volatile("ld.global.cs.v4.f32 {%0,%1,%2,%3}, [%4];"
        : "=f"(v.x), "=f"(v.y), "=f"(v.z), "=f"(v.w) : "l"(p));
    return v;
}
__device__ __forceinline__ float sigf(float x) {
    return __fdividef(1.0f, 1.0f + __expf(-x));
}
__device__ __forceinline__ float tanh_acc(float x) {
    return __fmaf_rn(2.0f, sigf(2.0f * x), -1.0f);
}
__device__ __forceinline__ uint32_t packh2(float a, float b) {
    __half2 v = __floats2half2_rn(a, b);
    return *reinterpret_cast<uint32_t*>(&v);
}

// ---------------- merged prep kernel (R14: 4x float4/thread, MLP=4, .cs) ----------------
static constexpr int PREP_A_BLOCKS = BB * (KK / 16) / 256;   // 4096
static constexpr int PREP_W_BLOCKS = NN * (KK / 16) / 256;   // 2048

__global__ void __launch_bounds__(256)
prep_all_kernel(const float* __restrict__ x, const float* __restrict__ h,
                const float* __restrict__ Wx, const float* __restrict__ bx,
                const float* __restrict__ Wh, const float* __restrict__ bh) {
#if __CUDA_ARCH__ >= 900
    cudaTriggerProgrammaticLaunchCompletion();
#endif
    const int blk = blockIdx.x;
    const float* srcbase;
    __half* dst;
    if (blk < PREP_A_BLOCKS) {
        int gid = blk * 256 + threadIdx.x;      // over BB * (KK/16)
        int row = gid >> 7;                     // KK/16 = 128 segments/row
        int seg = gid & 127;
        int d0  = seg << 4;
        srcbase = (d0 < DD) ? (x + (size_t)row * DD + d0)
                            : (h + (size_t)row * DD + (d0 - DD));
        dst = g_A + (size_t)row * KK + d0;
    } else {
        int gid = (blk - PREP_A_BLOCKS) * 256 + threadIdx.x;   // over NN * (KK/16)
        int row = gid >> 7;
        int seg = gid & 127;
        int d0  = seg << 4;
        int gate = row & 3;
        int hh   = row >> 2;
        int old  = (gate << 10) + hh;           // gate*1024 + h
        srcbase = (d0 < DD) ? (Wx + (size_t)old * DD + d0)
                            : (Wh + (size_t)old * DD + (d0 - DD));
        dst = g_W + (size_t)row * KK + d0;
        if (seg == 0) g_bias[row] = bx[old] + bh[old];
    }
    float4 v0 = ldcs4(srcbase);
    float4 v1 = ldcs4(srcbase + 4);
    float4 v2 = ldcs4(srcbase + 8);
    float4 v3 = ldcs4(srcbase + 12);
    uint4 o0, o1;
    o0.x = packh2(v0.x, v0.y);
    o0.y = packh2(v0.z, v0.w);
    o0.z = packh2(v1.x, v1.y);
    o0.w = packh2(v1.z, v1.w);
    o1.x = packh2(v2.x, v2.y);
    o1.y = packh2(v2.z, v2.w);
    o1.z = packh2(v3.x, v3.y);
    o1.w = packh2(v3.z, v3.w);
    *reinterpret_cast<uint4*>(dst)     = o0;
    *reinterpret_cast<uint4*>(dst + 8) = o1;
}

// ---------------- fused GEMM + LSTM gate kernel ----------------
// R15 champion + producer moved to loop BOTTOM (issues for kb+2 after this
// warp's own arrive, when the EMPTY wait is near-certainly already satisfied).
__global__ void __launch_bounds__(256, 2)
lstm_gemm_kernel(const __grid_constant__ CUtensorMap mapA,
                 const __grid_constant__ CUtensorMap mapB,
                 const float* __restrict__ c1_g,
                 float* __restrict__ h_out,
                 float* __restrict__ c_out) {
    extern __shared__ char smem_raw[];
    uint32_t s0   = s2u(smem_raw);
    uint32_t pad  = (1024u - (s0 & 1023u)) & 1023u;
    uint32_t sbase = s0 + pad;
    float* fbase = reinterpret_cast<float*>(smem_raw + pad);

    const int tid  = threadIdx.x;
    const int wid  = tid >> 5;
    const int lane = tid & 31;
    const int wm   = wid >> 1;            // 0..3 (m)
    const int wn   = wid & 1;             // 0..1 (n)
    const int m_base = blockIdx.y * BM;
    const int n_base = blockIdx.x * BN;
    const int h_base = blockIdx.x * (BN / 4);   // 32 h per tile

    const uint32_t FULL  = sbase + OFF_MBAR;          // full[s] : +8s
    const uint32_t EMPTY = sbase + OFF_MBAR + 8 * STAGES;

    if (tid == 0) {
        for (int s = 0; s < STAGES; s++) {
            mbar_init(FULL + 8 * s, 1);
            mbar_init(EMPTY + 8 * s, 8);   // one arrive per warp
        }
        asm volatile("fence.proxy.async.shared::cta;" ::: "memory");
    }
    __syncthreads();

    float acc[2][8][4];
    #pragma unroll
    for (int i = 0; i < 2; i++)
        #pragma unroll
        for (int j = 0; j < 8; j++)
            #pragma unroll
            for (int e = 0; e < 4; e++) acc[i][j][e] = 0.0f;

    const int lrow = lane & 15;     // ldmatrix row within 16
    const int lch  = lane >> 4;     // ldmatrix k half
    const int raA0 = wm * 32 + lrow;
    const int raA1 = raA0 + 16;
    const int rb0  = wn * 64 + lrow;

    const uint32_t offA0 = (uint32_t)(raA0 * 128) + (uint32_t)((lch ^ (raA0 & 7)) << 4);
    const uint32_t offA1 = (uint32_t)(raA1 * 128) + (uint32_t)((lch ^ (raA1 & 7)) << 4);
    uint32_t offB[4];
    #pragma unroll
    for (int nf2 = 0; nf2 < 4; nf2++) {
        int rb = rb0 + nf2 * 16;
        offB[nf2] = (uint32_t)A_STG + (uint32_t)(rb * 128)
                  + (uint32_t)((lch ^ (rb & 7)) << 4);
    }

#if __CUDA_ARCH__ >= 900
    // PDL: wait for prep grid to fully complete before consuming g_A/g_W/g_bias.
    cudaGridDependencySynchronize();
#endif

    // prologue: fill stages 0,1 (first data consumption — after gridsync)
    if (tid == 0) {
        #pragma unroll
        for (int s = 0; s < STAGES - 1; s++) {
            mbar_expect_tx(FULL + 8 * s, (uint32_t)STGB);
            uint32_t dA = sbase + s * STGB;
            tma_2d(dA,         &mapA, s * BK, m_base, FULL + 8 * s);
            tma_2d(dA + A_STG, &mapB, s * BK, n_base, FULL + 8 * s);
        }
    }

    // fragment double buffers
    uint32_t a0b[2][4], a1b[2][4], bfb[2][4][4];

    int b = 0, phase = 0;   // consumer stage index / parity (incremental)

    for (int kb = 0; kb < K_ITERS; kb++) {
        mbar_wait(FULL + 8 * b, phase);

        const uint32_t sA  = sbase + b * STGB;
        const uint32_t bA0 = sA + offA0;
        const uint32_t bA1 = sA + offA1;
        uint32_t bB[4];
        #pragma unroll
        for (int nf2 = 0; nf2 < 4; nf2++) bB[nf2] = sA + offB[nf2];

        // preload ks=0 fragments into buffer 0
        ldsm4(a0b[0], bA0);
        ldsm4(a1b[0], bA1);
        #pragma unroll
        for (int nf2 = 0; nf2 < 4; nf2++) ldsm4(bfb[0][nf2], bB[nf2]);

        #pragma unroll
        for (int ks = 0; ks < 4; ks++) {
            const int cur = ks & 1;
            if (ks < 3) {
                const uint32_t x5 = (uint32_t)((ks + 1) << 5);   // swizzle XOR step
                ldsm4(a0b[cur ^ 1], bA0 ^ x5);
                ldsm4(a1b[cur ^ 1], bA1 ^ x5);
                #pragma unroll
                for (int nf2 = 0; nf2 < 4; nf2++)
                    ldsm4(bfb[cur ^ 1][nf2], bB[nf2] ^ x5);
            }
            #pragma unroll
            for (int nf = 0; nf < 4; nf++) {
                mma16816(acc[0][2 * nf],     a0b[cur], bfb[cur][nf][0], bfb[cur][nf][2]);
                mma16816(acc[0][2 * nf + 1], a0b[cur], bfb[cur][nf][1], bfb[cur][nf][3]);
                mma16816(acc[1][2 * nf],     a1b[cur], bfb[cur][nf][0], bfb[cur][nf][2]);
                mma16816(acc[1][2 * nf + 1], a1b[cur], bfb[cur][nf][1], bfb[cur][nf][3]);
            }
        }
        if (lane == 0) mbar_arrive(EMPTY + 8 * b);

        // producer for chunk kb+2 — at loop BOTTOM: stragglers have drained
        // kb-1 by now, so the EMPTY wait is (near-)free. Prefetch distance
        // is one full chunk (~2000 cyc) >> TMA latency under this load.
        if (wid == (kb & 7) && lane == 0) {
            int nf = kb + STAGES - 1;                    // = kb + 2
            if (nf < K_ITERS) {
                int b2 = b + STAGES - 1;
                if (b2 >= STAGES) b2 -= STAGES;
                if (nf >= STAGES) {
                    mbar_wait(EMPTY + 8 * b2, ((nf - STAGES) / 3) & 1);
                }
                mbar_expect_tx(FULL + 8 * b2, (uint32_t)STGB);
                uint32_t dA = sbase + b2 * STGB;
                tma_2d(dA,         &mapA, nf * BK, m_base, FULL + 8 * b2);
                tma_2d(dA + A_STG, &mapB, nf * BK, n_base, FULL + 8 * b2);
            }
        }

        if (++b == STAGES) { b = 0; phase ^= 1; }
    }

    // -------- epilogue (register-prefetched) --------
    const int t    = lane & 3;           // quad col pair: local cols 2t, 2t+1
    const int rowg = lane >> 2;
    const bool evenT = (t & 1) == 0;     // holds (gi, gf); odd holds (go, gc)

    // 1) prefetch c1 tile rows (coalesced) + per-thread bias into registers
    //    BEFORE the barrier — latency overlaps the straggler wait.
    float4 c1r[4];
    #pragma unroll
    for (int i = 0; i < 4; i++) {
        int idx = tid + i * 256;                 // 1024 = 128*8 float4 slots
        int row = idx >> 3;
        int q   = idx & 7;
        c1r[i] = *reinterpret_cast<const float4*>(
            c1_g + (size_t)(m_base + row) * HDIM + h_base + q * 4);
    }
    float2 biasr[8];
    #pragma unroll
    for (int nj = 0; nj < 8; nj++) {
        biasr[nj] = *reinterpret_cast<const float2*>(
            g_bias + n_base + wn * 64 + nj * 8 + 2 * t);
    }

    __syncthreads();   // mainloop done -> stage buffers reusable

    // 2) spill prefetched c1 to smem (shared-layout exchange)
    #pragma unroll
    for (int i = 0; i < 4; i++) {
        int idx = tid + i * 256;
        int row = idx >> 3;
        int q   = idx & 7;
        *reinterpret_cast<float4*>(fbase + C1F + row * EPI_STRIDE + q * 4) = c1r[i];
    }
    __syncthreads();

    #pragma unroll
    for (int mf = 0; mf < 2; mf++) {
        const int rl0 = wm * 32 + mf * 16 + rowg;   // local row
        const int rl1 = rl0 + 8;
        #pragma unroll
        for (int nj = 0; nj < 8; nj++) {
            const float2 bias = biasr[nj];
            float g0a = acc[mf][nj][0] + bias.x;
            float g1a = acc[mf][nj][1] + bias.y;
            float g0b = acc[mf][nj][2] + bias.x;
            float g1b = acc[mf][nj][3] + bias.y;

            float pa = sigf(g0a);
            float qa = evenT ? sigf(g1a) : tanh_acc(g1a);
            float pb = sigf(g0b);
            float qb = evenT ? sigf(g1b) : tanh_acc(g1b);

            float ov_a = __shfl_xor_sync(0xFFFFFFFFu, pa, 1);
            float ct_a = __shfl_xor_sync(0xFFFFFFFFu, qa, 1);
            float ov_b = __shfl_xor_sync(0xFFFFFFFFu, pb, 1);
            float ct_b = __shfl_xor_sync(0xFFFFFFFFu, qb, 1);

            const int hl = wn * 16 + nj * 2 + (t >> 1);
            float cna = 0.f, cnb = 0.f, hna = 0.f, hnb = 0.f;
            if (evenT) {
                float c1a = fbase[C1F + rl0 * EPI_STRIDE + hl];
                float c1b = fbase[C1F + rl1 * EPI_STRIDE + hl];
                cna = sigf(qa * c1a + pa * ct_a);
                cnb = sigf(qb * c1b + pb * ct_b);
                hna = tanh_acc(cna) * ov_a;
                hnb = tanh_acc(cnb) * ov_b;
            }
            float cna2 = __shfl_xor_sync(0xFFFFFFFFu, cna, 2);
            float cnb2 = __shfl_xor_sync(0xFFFFFFFFu, cnb, 2);
            float hna2 = __shfl_xor_sync(0xFFFFFFFFu, hna, 2);
            float hnb2 = __shfl_xor_sync(0xFFFFFFFFu, hnb, 2);
            if (t == 0) {
                const int c2 = wn * 16 + nj * 2;
                *reinterpret_cast<float2*>(fbase + HSF + rl0 * EPI_STRIDE + c2) =
                    make_float2(hna, hna2);
                *reinterpret_cast<float2*>(fbase + HSF + rl1 * EPI_STRIDE + c2) =
                    make_float2(hnb, hnb2);
                *reinterpret_cast<float2*>(fbase + CSF + rl0 * EPI_STRIDE + c2) =
                    make_float2(cna, cna2);
                *reinterpret_cast<float2*>(fbase + CSF + rl1 * EPI_STRIDE + c2) =
                    make_float2(cnb, cnb2);
            }
        }
    }
    __syncthreads();

    // coalesced global stores
    for (int idx = tid; idx < 128 * 8; idx += 256) {
        int row = idx >> 3;
        int q   = idx & 7;
        float4 hv = *reinterpret_cast<const float4*>(fbase + HSF + row * EPI_STRIDE + q * 4);
        float4 cv = *reinterpret_cast<const float4*>(fbase + CSF + row * EPI_STRIDE + q * 4);
        size_t off = (size_t)(m_base + row) * HDIM + h_base + q * 4;
        *reinterpret_cast<float4*>(h_out + off) = hv;
        *reinterpret_cast<float4*>(c_out + off) = cv;
    }
}

// ---------------- host launcher ----------------
typedef CUresult (*tme_fn_t)(CUtensorMap*, CUtensorMapDataType, cuuint32_t, void*,
                             const cuuint64_t*, const cuuint64_t*, const cuuint32_t*,
                             const cuuint32_t*, CUtensorMapInterleave, CUtensorMapSwizzle,
                             CUtensorMapL2promotion, CUtensorMapFloatOOBfill);

static tme_fn_t get_encoder() {
    void* fn = nullptr;
    cudaDriverEntryPointQueryResult qr;
#if CUDART_VERSION >= 12050
    cudaGetDriverEntryPointByVersion("cuTensorMapEncodeTiled", &fn, 12000,
                                     cudaEnableDefault, &qr);
#else
    cudaGetDriverEntryPoint("cuTensorMapEncodeTiled", &fn, cudaEnableDefault, &qr);
#endif
    return (tme_fn_t)fn;
}

extern "C" void kernel_launch(void* const* d_in, const int* in_sizes, int n_in,
                              void* d_out, int out_size) {
    const float* x  = (const float*)d_in[0];
    const float* h  = (const float*)d_in[1];
    const float* c1 = (const float*)d_in[2];
    const float* Wx = (const float*)d_in[3];
    const float* bx = (const float*)d_in[4];
    const float* Wh = (const float*)d_in[5];
    const float* bh = (const float*)d_in[6];
    float* h_out = (float*)d_out;
    float* c_out = h_out + (size_t)BB * HDIM;

    prep_all_kernel<<<PREP_A_BLOCKS + PREP_W_BLOCKS, 256>>>(x, h, Wx, bx, Wh, bh);

    void* aptr = nullptr; void* wptr = nullptr;
    cudaGetSymbolAddress(&aptr, g_A);
    cudaGetSymbolAddress(&wptr, g_W);
    tme_fn_t enc = get_encoder();
    if (!enc) return;

    CUtensorMap mapA, mapB;
    cuuint64_t dimsA[2] = {(cuuint64_t)KK, (cuuint64_t)BB};
    cuuint64_t strA[1]  = {(cuuint64_t)KK * 2};
    cuuint32_t boxA[2]  = {BK, BM};
    cuuint32_t es[2]    = {1, 1};
    enc(&mapA, CU_TENSOR_MAP_DATA_TYPE_FLOAT16, 2, aptr, dimsA, strA, boxA, es,
        CU_TENSOR_MAP_INTERLEAVE_NONE, CU_TENSOR_MAP_SWIZZLE_128B,
        CU_TENSOR_MAP_L2_PROMOTION_L2_128B, CU_TENSOR_MAP_FLOAT_OOB_FILL_NONE);

    cuuint64_t dimsB[2] = {(cuuint64_t)KK, (cuuint64_t)NN};
    cuuint32_t boxB[2]  = {BK, BN};
    enc(&mapB, CU_TENSOR_MAP_DATA_TYPE_FLOAT16, 2, wptr, dimsB, strA, boxB, es,
        CU_TENSOR_MAP_INTERLEAVE_NONE, CU_TENSOR_MAP_SWIZZLE_128B,
        CU_TENSOR_MAP_L2_PROMOTION_L2_128B, CU_TENSOR_MAP_FLOAT_OOB_FILL_NONE);

    cudaFuncSetAttribute(lstm_gemm_kernel,
                         cudaFuncAttributeMaxDynamicSharedMemorySize, SMEM_DYN);

    // PDL launch: GEMM prologue overlaps prep drain; gridsync enforces data dep.
    cudaLaunchConfig_t cfg = {};
    cfg.gridDim  = dim3(NN / BN, BB / BM, 1);   // (32, 64)
    cfg.blockDim = dim3(256, 1, 1);
    cfg.dynamicSmemBytes = SMEM_DYN;
    cfg.stream = 0;
    cudaLaunchAttribute attrs[1];
    attrs[0].id = cudaLaunchAttributeProgrammaticStreamSerialization;
    attrs[0].val.programmaticStreamSerializationAllowed = 1;
    cfg.attrs = attrs;
    cfg.numAttrs = 1;
    cudaError_t err = cudaLaunchKernelEx(&cfg, lstm_gemm_kernel,
                                         mapA, mapB, c1, h_out, c_out);
    if (err != cudaSuccess) {
        lstm_gemm_kernel<<<dim3(NN / BN, BB / BM), 256, SMEM_DYN>>>(
            mapA, mapB, c1, h_out, c_out);
    }
}